// round 15
// baseline (speedup 1.0000x reference)
#include <cuda_runtime.h>
#include <cstdint>

// Problem constants (fixed shapes for this problem instance)
#define N_MASKS 128
#define HM 28
#define WM 28
#define IMG_H 800
#define IMG_W 1280
#define IN_W 1184.0f
#define IN_H 736.0f
#define ROWS_PER_BLOCK 4

// Block = 4 consecutive rows of one mask. 320 threads, thread t owns pixels
// [4t,4t+3] in each of 4 rows -> 4x STG.128 streaming stores.
// Zero path (91% of threads): LDG.128 box -> 2 FSUB -> 4 FMA -> 4 FSETP -> STG.
// __launch_bounds__(320,5): cap regs at 40 for 5 resident blocks (50 warps/SM)
// to deepen the in-flight store queue; any spill pressure lands only in the
// active path (~9% of threads).
__global__ void __launch_bounds__(320, 5)
paste_kernel(const float* __restrict__ masks,
             const float4* __restrict__ boxes,
             float* __restrict__ out) {
    const int n  = blockIdx.y;
    const int y0 = blockIdx.x * ROWS_PER_BLOCK;
    const int x4 = threadIdx.x * 4;

    const float sx = (float)IMG_W / IN_W;
    const float sy = (float)IMG_H / IN_H;
    float4 bxy = __ldg(boxes + n);
    float bx0 = bxy.x * sx;
    float by0 = bxy.y * sy;
    float dx  = (bxy.z - bxy.x) * sx;     // > 0 (boxes have min extent 16)
    float dy  = (bxy.w - bxy.y) * sy;     // > 0

    float* dst = out + ((size_t)n * IMG_H + y0) * IMG_W + x4;
    const float4 zero = make_float4(0.f, 0.f, 0.f, 0.f);

    // Support bounds in image coords:
    //   px > -1  <=>  x+0.5 > bx0 - dx/(2*WM)
    //   px < WM  <=>  x+0.5 < bx0 + dx*(1 + 1/(2*WM))
    const float C1 = 1.0f / (2.0f * (float)WM);        // 1/56 (WM==HM==28)
    const float C2 = 1.0f + C1;                        // 57/56
    float xlo = bx0 - dx * C1;
    float xhi = bx0 + dx * C2;
    float ylo = by0 - dy * C1;
    float yhi = by0 + dy * C2;

    float xf = (float)x4 + 0.5f;     // first pixel center
    float yf = (float)y0 + 0.5f;
    bool active = (xf + 3.0f > xlo) & (xf < xhi) &
                  (yf + 3.0f > ylo) & (yf < yhi);

    if (!active) {
        // Fast path: 4 independent streaming zero stores (MLP=4).
#pragma unroll
        for (int r = 0; r < ROWS_PER_BLOCK; r++)
            __stcs(reinterpret_cast<float4*>(dst + (size_t)r * IMG_W), zero);
        return;
    }

    // ---- active path: pay for the reciprocals here only ----
    float ax = __fdividef((float)WM, dx);
    float ay = __fdividef((float)HM, dy);
    float px0 = (xf - bx0) * ax - 0.5f;
    float py0 = (yf - by0) * ay - 0.5f;

    // horizontal precompute (shared by all 4 rows)
    int   ix0[4], ix1[4];
    float w0[4], w1[4];
#pragma unroll
    for (int k = 0; k < 4; k++) {
        float px  = px0 + (float)k * ax;
        float fx  = floorf(px);
        int   ix  = (int)fx;
        float wx1 = px - fx;
        float wx0 = 1.0f - wx1;
        bool inr = (px > -1.0f) & (px < (float)WM);
        bool vx0 = inr & (ix >= 0);
        bool vx1 = inr & (ix + 1 < WM);
        w0[k]  = vx0 ? wx0 : 0.0f;
        w1[k]  = vx1 ? wx1 : 0.0f;
        ix0[k] = min(max(ix, 0), WM - 1);
        ix1[k] = min(max(ix + 1, 0), WM - 1);
    }

    const float* mbase = masks + (size_t)n * (HM * WM);

#pragma unroll
    for (int r = 0; r < ROWS_PER_BLOCK; r++) {
        float py  = py0 + (float)r * ay;
        float fy  = floorf(py);
        int   iy  = (int)fy;
        float wy1 = py - fy;
        float wy0 = 1.0f - wy1;
        bool inr = (py > -1.0f) & (py < (float)HM);
        float wr0 = (inr & (iy >= 0))     ? wy0 : 0.0f;
        float wr1 = (inr & (iy + 1 < HM)) ? wy1 : 0.0f;
        const float* r0 = mbase + min(max(iy, 0), HM - 1) * WM;
        const float* r1 = mbase + min(max(iy + 1, 0), HM - 1) * WM;

        float res[4];
#pragma unroll
        for (int k = 0; k < 4; k++) {
            float top = w0[k] * __ldg(r0 + ix0[k]) + w1[k] * __ldg(r0 + ix1[k]);
            float bot = w0[k] * __ldg(r1 + ix0[k]) + w1[k] * __ldg(r1 + ix1[k]);
            res[k] = wr0 * top + wr1 * bot;
        }
        __stcs(reinterpret_cast<float4*>(dst + (size_t)r * IMG_W),
               make_float4(res[0], res[1], res[2], res[3]));
    }
}

extern "C" void kernel_launch(void* const* d_in, const int* in_sizes, int n_in,
                              void* d_out, int out_size) {
    const float* masks  = (const float*)d_in[0];
    const float4* boxes = (const float4*)d_in[1];
    float* out = (float*)d_out;

    dim3 grid(IMG_H / ROWS_PER_BLOCK, N_MASKS);   // (200, 128)
    paste_kernel<<<grid, 320>>>(masks, boxes, out);
}

// round 17
// speedup vs baseline: 1.0051x; 1.0051x over previous
#include <cuda_runtime.h>
#include <cstdint>

// Problem constants (fixed shapes for this problem instance)
#define N_MASKS 128
#define HM 28
#define WM 28
#define IMG_H 800
#define IMG_W 1280
#define IN_W 1184.0f
#define IN_H 736.0f
#define ROWS_PER_BLOCK 4

// R13 champion shape (320 thr, 4 rows/block, float4 __stcs, ~47 regs, no
// occupancy cap) with ONE change: grid dims swapped (x=mask, y=row-group) so
// the concurrently-resident CTAs write one row-band across all 128 mask
// images (128 regions at 4MB stride) instead of consecutive strips of ~5
// masks -- maximizes HBM channel/bank parallelism of the write stream.
__global__ void __launch_bounds__(320)
paste_kernel(const float* __restrict__ masks,
             const float4* __restrict__ boxes,
             float* __restrict__ out) {
    const int n  = blockIdx.x;                       // mask index (swapped)
    const int y0 = blockIdx.y * ROWS_PER_BLOCK;      // row group   (swapped)
    const int x4 = threadIdx.x * 4;

    const float sx = (float)IMG_W / IN_W;
    const float sy = (float)IMG_H / IN_H;
    float4 bxy = __ldg(boxes + n);
    float bx0 = bxy.x * sx;
    float by0 = bxy.y * sy;
    float dx  = (bxy.z - bxy.x) * sx;     // > 0 (boxes have min extent 16)
    float dy  = (bxy.w - bxy.y) * sy;     // > 0

    float* dst = out + ((size_t)n * IMG_H + y0) * IMG_W + x4;
    const float4 zero = make_float4(0.f, 0.f, 0.f, 0.f);

    // Division-free support bounds in image coords:
    //   px > -1  <=>  x+0.5 > bx0 - dx/(2*WM)
    //   px < WM  <=>  x+0.5 < bx0 + dx*(1 + 1/(2*WM))
    const float C1 = 1.0f / (2.0f * (float)WM);        // 1/56 (WM==HM==28)
    const float C2 = 1.0f + C1;                        // 57/56
    float xlo = bx0 - dx * C1;
    float xhi = bx0 + dx * C2;
    float ylo = by0 - dy * C1;
    float yhi = by0 + dy * C2;

    float xf = (float)x4 + 0.5f;     // first pixel center
    float yf = (float)y0 + 0.5f;
    bool active = (xf + 3.0f > xlo) & (xf < xhi) &
                  (yf + 3.0f > ylo) & (yf < yhi);

    if (!active) {
        // Fast path: 4 independent streaming zero stores (MLP=4).
#pragma unroll
        for (int r = 0; r < ROWS_PER_BLOCK; r++)
            __stcs(reinterpret_cast<float4*>(dst + (size_t)r * IMG_W), zero);
        return;
    }

    // ---- active path: pay for the reciprocals here only ----
    float ax = __fdividef((float)WM, dx);
    float ay = __fdividef((float)HM, dy);
    float px0 = (xf - bx0) * ax - 0.5f;
    float py0 = (yf - by0) * ay - 0.5f;

    // horizontal precompute (shared by all 4 rows)
    int   ix0[4], ix1[4];
    float w0[4], w1[4];
#pragma unroll
    for (int k = 0; k < 4; k++) {
        float px  = px0 + (float)k * ax;
        float fx  = floorf(px);
        int   ix  = (int)fx;
        float wx1 = px - fx;
        float wx0 = 1.0f - wx1;
        bool inr = (px > -1.0f) & (px < (float)WM);
        bool vx0 = inr & (ix >= 0);
        bool vx1 = inr & (ix + 1 < WM);
        w0[k]  = vx0 ? wx0 : 0.0f;
        w1[k]  = vx1 ? wx1 : 0.0f;
        ix0[k] = min(max(ix, 0), WM - 1);
        ix1[k] = min(max(ix + 1, 0), WM - 1);
    }

    const float* mbase = masks + (size_t)n * (HM * WM);

#pragma unroll
    for (int r = 0; r < ROWS_PER_BLOCK; r++) {
        float py  = py0 + (float)r * ay;
        float fy  = floorf(py);
        int   iy  = (int)fy;
        float wy1 = py - fy;
        float wy0 = 1.0f - wy1;
        bool inr = (py > -1.0f) & (py < (float)HM);
        float wr0 = (inr & (iy >= 0))     ? wy0 : 0.0f;
        float wr1 = (inr & (iy + 1 < HM)) ? wy1 : 0.0f;
        const float* r0 = mbase + min(max(iy, 0), HM - 1) * WM;
        const float* r1 = mbase + min(max(iy + 1, 0), HM - 1) * WM;

        float res[4];
#pragma unroll
        for (int k = 0; k < 4; k++) {
            float top = w0[k] * __ldg(r0 + ix0[k]) + w1[k] * __ldg(r0 + ix1[k]);
            float bot = w0[k] * __ldg(r1 + ix0[k]) + w1[k] * __ldg(r1 + ix1[k]);
            res[k] = wr0 * top + wr1 * bot;
        }
        __stcs(reinterpret_cast<float4*>(dst + (size_t)r * IMG_W),
               make_float4(res[0], res[1], res[2], res[3]));
    }
}

extern "C" void kernel_launch(void* const* d_in, const int* in_sizes, int n_in,
                              void* d_out, int out_size) {
    const float* masks  = (const float*)d_in[0];
    const float4* boxes = (const float4*)d_in[1];
    float* out = (float*)d_out;

    dim3 grid(N_MASKS, IMG_H / ROWS_PER_BLOCK);   // (128, 200) -- swapped
    paste_kernel<<<grid, 320>>>(masks, boxes, out);
}